// round 1
// baseline (speedup 1.0000x reference)
#include <cuda_runtime.h>
#include <cstdint>

// ---------------------------------------------------------------------------
// DeformRoIPooling (deformable PS-RoI pooling), GROUP_SIZE=1 specialization.
//
// data:   (B=2, C=256, H=128, W=128) f32
// rois:   (N=128, 5) f32  [b, x1, y1, x2, y2]
// offset: (N=128, 2, 7, 7) f32
// out:    (N=128, 256, 7, 7) f32
//
// Strategy:
//   1) transpose data -> (B, H, W, C) scratch so the per-corner channel
//      gather (256 floats) is a contiguous 1KB burst (coalesced L2 reads).
//   2) one 64-thread block per (roi, bin); thread t owns channels 4t..4t+3
//      via float4. Sample grid (4x4) identical across channels -> computed
//      once per block (uniform branches, no divergence).
// ---------------------------------------------------------------------------

#define BQ   2
#define CQ   256
#define HQ   128
#define WQ   128
#define NROI 128
#define PQ   7
#define SQ   4
#define SPATIAL_SCALE 0.0625f
#define TRANS_STD 0.1f

// 32 MB transposed scratch: (B, H, W, C)
__device__ float g_tdata[(size_t)BQ * HQ * WQ * CQ];

// ---------------------------------------------------------------------------
// Transpose: per batch, (C=256) x (HW=16384) matrix -> (HW) x (C).
// 32x32 smem tiles, both sides coalesced.
// ---------------------------------------------------------------------------
__global__ void transpose_kernel(const float* __restrict__ src) {
    __shared__ float tile[32][33];
    const int b   = blockIdx.z;
    const int hw0 = blockIdx.x * 32;
    const int c0  = blockIdx.y * 32;
    const float* s = src + (size_t)b * CQ * HQ * WQ;
    float* d       = g_tdata + (size_t)b * HQ * WQ * CQ;

    const int tx = threadIdx.x;   // 0..31
    #pragma unroll
    for (int i = threadIdx.y; i < 32; i += 8) {
        tile[i][tx] = s[(size_t)(c0 + i) * (HQ * WQ) + hw0 + tx];
    }
    __syncthreads();
    #pragma unroll
    for (int i = threadIdx.y; i < 32; i += 8) {
        d[(size_t)(hw0 + i) * CQ + c0 + tx] = tile[tx][i];
    }
}

// ---------------------------------------------------------------------------
// Pool: block = (bin, roi), 64 threads, thread t -> channels 4t..4t+3.
// ---------------------------------------------------------------------------
__global__ void __launch_bounds__(64) pool_kernel(
    const float* __restrict__ rois,
    const float* __restrict__ offset,
    float* __restrict__ out)
{
    const int bin = blockIdx.x;        // 0..48
    const int n   = blockIdx.y;        // 0..127
    const int ph  = bin / PQ;
    const int pw  = bin - ph * PQ;
    const int t   = threadIdx.x;       // 0..63

    // --- geometry (uniform across block; replicate reference IEEE f32 ops) ---
    const float* r = rois + n * 5;
    const int   b  = (int)r[0];
    const float rsw = rintf(r[1]) * SPATIAL_SCALE - 0.5f;
    const float rsh = rintf(r[2]) * SPATIAL_SCALE - 0.5f;
    const float rew = (rintf(r[3]) + 1.0f) * SPATIAL_SCALE - 0.5f;
    const float reh = (rintf(r[4]) + 1.0f) * SPATIAL_SCALE - 0.5f;
    const float rw = fmaxf(rew - rsw, 0.1f);
    const float rh = fmaxf(reh - rsh, 0.1f);
    const float binw = rw / (float)PQ;
    const float binh = rh / (float)PQ;
    const float subw = binw / (float)SQ;
    const float subh = binh / (float)SQ;

    // part indices: floor(p/P * PART_SIZE) with the same f32 ops as reference
    const int part_h = (int)floorf((float)ph / (float)PQ * (float)PQ);
    const int part_w = (int)floorf((float)pw / (float)PQ * (float)PQ);

    const float tx_off = offset[n * (2 * PQ * PQ) + part_h * PQ + part_w] * TRANS_STD;
    const float ty_off = offset[n * (2 * PQ * PQ) + PQ * PQ + part_h * PQ + part_w] * TRANS_STD;

    const float wstart = (float)pw * binw + rsw + tx_off * rw;
    const float hstart = (float)ph * binh + rsh + ty_off * rh;

    const float* base = g_tdata + (size_t)b * HQ * WQ * CQ;

    float4 acc = make_float4(0.f, 0.f, 0.f, 0.f);
    float count = 0.f;

    #pragma unroll
    for (int ih = 0; ih < SQ; ih++) {
        const float h  = hstart + (float)ih * subh;
        const bool  vh = (h >= -0.5f) && (h <= (float)HQ - 0.5f);
        const float hc = fminf(fmaxf(h, 0.f), (float)(HQ - 1));
        const float y0f = floorf(hc);
        const float y1f = ceilf(hc);
        const float dy  = hc - y0f;
        const int y0 = (int)y0f;
        const int y1 = (int)y1f;

        #pragma unroll
        for (int iw = 0; iw < SQ; iw++) {
            const float w  = wstart + (float)iw * subw;
            const bool  vw = (w >= -0.5f) && (w <= (float)WQ - 0.5f);
            if (!(vh && vw)) continue;     // uniform across block
            count += 1.0f;

            const float wc = fminf(fmaxf(w, 0.f), (float)(WQ - 1));
            const float x0f = floorf(wc);
            const float x1f = ceilf(wc);
            const float dx  = wc - x0f;
            const int x0 = (int)x0f;
            const int x1 = (int)x1f;

            const float w00 = (1.f - dy) * (1.f - dx);
            const float w01 = (1.f - dy) * dx;
            const float w10 = dy * (1.f - dx);
            const float w11 = dy * dx;

            const float4* p00 = (const float4*)(base + ((y0 * WQ + x0) * CQ)) + t;
            const float4* p01 = (const float4*)(base + ((y0 * WQ + x1) * CQ)) + t;
            const float4* p10 = (const float4*)(base + ((y1 * WQ + x0) * CQ)) + t;
            const float4* p11 = (const float4*)(base + ((y1 * WQ + x1) * CQ)) + t;

            const float4 v00 = __ldg(p00);
            const float4 v01 = __ldg(p01);
            const float4 v10 = __ldg(p10);
            const float4 v11 = __ldg(p11);

            acc.x += w00 * v00.x + w01 * v01.x + w10 * v10.x + w11 * v11.x;
            acc.y += w00 * v00.y + w01 * v01.y + w10 * v10.y + w11 * v11.y;
            acc.z += w00 * v00.z + w01 * v01.z + w10 * v10.z + w11 * v11.z;
            acc.w += w00 * v00.w + w01 * v01.w + w10 * v10.w + w11 * v11.w;
        }
    }

    float4 res;
    if (count > 0.f) {
        res.x = acc.x / count;
        res.y = acc.y / count;
        res.z = acc.z / count;
        res.w = acc.w / count;
    } else {
        res = make_float4(0.f, 0.f, 0.f, 0.f);
    }

    // out layout (N, C, 7, 7): channel stride = 49
    float* o = out + ((size_t)n * CQ + 4 * t) * (PQ * PQ) + ph * PQ + pw;
    o[0]          = res.x;
    o[PQ * PQ]    = res.y;
    o[2 * PQ * PQ] = res.z;
    o[3 * PQ * PQ] = res.w;
}

extern "C" void kernel_launch(void* const* d_in, const int* in_sizes, int n_in,
                              void* d_out, int out_size) {
    const float* data   = (const float*)d_in[0];
    const float* rois   = (const float*)d_in[1];
    const float* offset = (const float*)d_in[2];
    float* out = (float*)d_out;

    // 1) transpose (B,C,H,W) -> (B,H,W,C)
    dim3 tg(HQ * WQ / 32, CQ / 32, BQ);     // (512, 8, 2)
    dim3 tb(32, 8);
    transpose_kernel<<<tg, tb>>>(data);

    // 2) pool: one block per (bin, roi)
    dim3 pg(PQ * PQ, NROI);                 // (49, 128)
    pool_kernel<<<pg, 64>>>(rois, offset, out);
}

// round 2
// speedup vs baseline: 1.0453x; 1.0453x over previous
#include <cuda_runtime.h>
#include <cstdint>

// ---------------------------------------------------------------------------
// DeformRoIPooling (deformable PS-RoI pooling), GROUP_SIZE=1 specialization.
//
// data:   (B=2, C=256, H=128, W=128) f32
// rois:   (N=128, 5) f32  [b, x1, y1, x2, y2]
// offset: (N=128, 2, 7, 7) f32
// out:    (N=128, 256, 7, 7) f32
//
// R2: packed f32x2 FMA accumulation (FFMA2), 4 bins per 256-thread block,
//     float4-vectorized transpose.
// ---------------------------------------------------------------------------

#define BQ   2
#define CQ   256
#define HQ   128
#define WQ   128
#define NROI 128
#define PQ   7
#define SQ   4
#define SPATIAL_SCALE 0.0625f
#define TRANS_STD 0.1f

// 32 MB transposed scratch: (B, H, W, C) — lives in L2 (126MB)
__device__ float g_tdata[(size_t)BQ * HQ * WQ * CQ];

// ---------------------------------------------------------------------------
// Vectorized transpose: per batch, (C=256) x (P=16384) -> (P) x (C).
// Tile = 32 channels x 64 positions, float4 loads AND float4 stores.
// ---------------------------------------------------------------------------
__global__ void __launch_bounds__(256) transpose_kernel(const float* __restrict__ src) {
    __shared__ float tile[32][68];          // pitch 68: aligned STS.128, ~2-way LDS conflicts
    const int b  = blockIdx.z;
    const int c0 = blockIdx.y * 32;
    const int p0 = blockIdx.x * 64;
    const float* s = src + ((size_t)b * CQ + c0) * (HQ * WQ) + p0;
    float* d       = g_tdata + (size_t)b * HQ * WQ * CQ;

    const int i = threadIdx.x;

    // Load: 32 c-rows x 16 float4 (64 p) = 512 float4; 2 per thread. Coalesced.
    {
        const int c = i >> 4;               // 0..15
        const int q = i & 15;               // 0..15
        #pragma unroll
        for (int r = 0; r < 2; r++) {
            float4 v = *(const float4*)(s + (size_t)(c + 16 * r) * (HQ * WQ) + 4 * q);
            *(float4*)&tile[c + 16 * r][4 * q] = v;
        }
    }
    __syncthreads();

    // Store: 64 p-rows x 8 float4 (32 c) = 512 float4; 2 per thread. Coalesced.
    {
        const int p   = i >> 2;             // 0..63
        const int cq0 = i & 3;              // 0..3
        #pragma unroll
        for (int r = 0; r < 2; r++) {
            const int cq = cq0 + 4 * r;     // 0..7
            float4 v;
            v.x = tile[4 * cq + 0][p];
            v.y = tile[4 * cq + 1][p];
            v.z = tile[4 * cq + 2][p];
            v.w = tile[4 * cq + 3][p];
            *(float4*)(d + (size_t)(p0 + p) * CQ + c0 + 4 * cq) = v;
        }
    }
}

// ---------------------------------------------------------------------------
// Packed f32x2 helpers (Blackwell FFMA2 via PTX)
// ---------------------------------------------------------------------------
__device__ __forceinline__ unsigned long long pack2(float v) {
    unsigned long long r;
    asm("mov.b64 %0, {%1, %1};" : "=l"(r) : "f"(v));
    return r;
}
__device__ __forceinline__ void fma2(unsigned long long& d,
                                     unsigned long long a,
                                     unsigned long long b) {
    asm("fma.rn.f32x2 %0, %1, %2, %0;" : "+l"(d) : "l"(a), "l"(b));
}
__device__ __forceinline__ void unpack2(unsigned long long v, float& lo, float& hi) {
    asm("mov.b64 {%0, %1}, %2;" : "=f"(lo), "=f"(hi) : "l"(v));
}

// ---------------------------------------------------------------------------
// Pool: block = 256 threads = 4 bins x 64 threads. thread.x t -> channels 4t..4t+3.
// Warps never span bins (warp = 32 consecutive x within one y) -> uniform branches.
// ---------------------------------------------------------------------------
__global__ void __launch_bounds__(256) pool_kernel(
    const float* __restrict__ rois,
    const float* __restrict__ offset,
    float* __restrict__ out)
{
    const int bin = blockIdx.x * 4 + threadIdx.y;  // 0..51
    if (bin >= PQ * PQ) return;
    const int n   = blockIdx.y;                    // 0..127
    const int ph  = bin / PQ;
    const int pw  = bin - ph * PQ;
    const int t   = threadIdx.x;                   // 0..63

    // --- geometry (uniform across the bin; replicate reference IEEE f32 ops) ---
    const float* r = rois + n * 5;
    const int   b  = (int)__ldg(&r[0]);
    const float rsw = rintf(__ldg(&r[1])) * SPATIAL_SCALE - 0.5f;
    const float rsh = rintf(__ldg(&r[2])) * SPATIAL_SCALE - 0.5f;
    const float rew = (rintf(__ldg(&r[3])) + 1.0f) * SPATIAL_SCALE - 0.5f;
    const float reh = (rintf(__ldg(&r[4])) + 1.0f) * SPATIAL_SCALE - 0.5f;
    const float rw = fmaxf(rew - rsw, 0.1f);
    const float rh = fmaxf(reh - rsh, 0.1f);
    const float binw = rw / (float)PQ;
    const float binh = rh / (float)PQ;
    const float subw = binw / (float)SQ;
    const float subh = binh / (float)SQ;

    // part indices with the same f32 ops as reference
    const int part_h = (int)floorf((float)ph / (float)PQ * (float)PQ);
    const int part_w = (int)floorf((float)pw / (float)PQ * (float)PQ);

    const float tx_off = __ldg(&offset[n * (2 * PQ * PQ) + part_h * PQ + part_w]) * TRANS_STD;
    const float ty_off = __ldg(&offset[n * (2 * PQ * PQ) + PQ * PQ + part_h * PQ + part_w]) * TRANS_STD;

    const float wstart = (float)pw * binw + rsw + tx_off * rw;
    const float hstart = (float)ph * binh + rsh + ty_off * rh;

    const float* base = g_tdata + (size_t)b * HQ * WQ * CQ;

    unsigned long long acc01 = 0ull, acc23 = 0ull;   // packed {f32,f32} accumulators
    float count = 0.f;

    #pragma unroll
    for (int ih = 0; ih < SQ; ih++) {
        const float h  = hstart + (float)ih * subh;
        const bool  vh = (h >= -0.5f) && (h <= (float)HQ - 0.5f);
        const float hc = fminf(fmaxf(h, 0.f), (float)(HQ - 1));
        const float y0f = floorf(hc);
        const float dy  = hc - y0f;
        const int y0 = (int)y0f;
        const int y1 = (int)ceilf(hc);

        #pragma unroll
        for (int iw = 0; iw < SQ; iw++) {
            const float w  = wstart + (float)iw * subw;
            const bool  vw = (w >= -0.5f) && (w <= (float)WQ - 0.5f);
            if (!(vh && vw)) continue;               // uniform per warp
            count += 1.0f;

            const float wc = fminf(fmaxf(w, 0.f), (float)(WQ - 1));
            const float x0f = floorf(wc);
            const float dx  = wc - x0f;
            const int x0 = (int)x0f;
            const int x1 = (int)ceilf(wc);

            const unsigned long long w00 = pack2((1.f - dy) * (1.f - dx));
            const unsigned long long w01 = pack2((1.f - dy) * dx);
            const unsigned long long w10 = pack2(dy * (1.f - dx));
            const unsigned long long w11 = pack2(dy * dx);

            const ulonglong2 v00 = __ldg((const ulonglong2*)(base + (y0 * WQ + x0) * CQ) + t);
            const ulonglong2 v01 = __ldg((const ulonglong2*)(base + (y0 * WQ + x1) * CQ) + t);
            const ulonglong2 v10 = __ldg((const ulonglong2*)(base + (y1 * WQ + x0) * CQ) + t);
            const ulonglong2 v11 = __ldg((const ulonglong2*)(base + (y1 * WQ + x1) * CQ) + t);

            fma2(acc01, w00, v00.x);  fma2(acc23, w00, v00.y);
            fma2(acc01, w01, v01.x);  fma2(acc23, w01, v01.y);
            fma2(acc01, w10, v10.x);  fma2(acc23, w10, v10.y);
            fma2(acc01, w11, v11.x);  fma2(acc23, w11, v11.y);
        }
    }

    float a0, a1, a2, a3;
    unpack2(acc01, a0, a1);
    unpack2(acc23, a2, a3);

    float r0 = 0.f, r1 = 0.f, r2 = 0.f, r3 = 0.f;
    if (count > 0.f) {
        const float inv = 1.0f / count;   // exact-enough; ref does a/b with b=count
        r0 = a0 / count; r1 = a1 / count; r2 = a2 / count; r3 = a3 / count;
        (void)inv;
    }

    // out layout (N, C, 7, 7): channel stride = 49
    float* o = out + ((size_t)n * CQ + 4 * t) * (PQ * PQ) + ph * PQ + pw;
    o[0]            = r0;
    o[PQ * PQ]      = r1;
    o[2 * PQ * PQ]  = r2;
    o[3 * PQ * PQ]  = r3;
}

extern "C" void kernel_launch(void* const* d_in, const int* in_sizes, int n_in,
                              void* d_out, int out_size) {
    const float* data   = (const float*)d_in[0];
    const float* rois   = (const float*)d_in[1];
    const float* offset = (const float*)d_in[2];
    float* out = (float*)d_out;

    // 1) transpose (B,C,H,W) -> (B,H,W,C)
    dim3 tg(HQ * WQ / 64, CQ / 32, BQ);     // (256, 8, 2)
    transpose_kernel<<<tg, 256>>>(data);

    // 2) pool: 4 bins per 256-thread block
    dim3 pg((PQ * PQ + 3) / 4, NROI);       // (13, 128)
    dim3 pb(64, 4);
    pool_kernel<<<pg, pb>>>(rois, offset, out);
}